// round 11
// baseline (speedup 1.0000x reference)
#include <cuda_runtime.h>
#include <cuda_bf16.h>

// NMS: B=32, N=2048, keep first R=100 surviving boxes (greedy, score-desc).
// pred: [B, N, 5] = (score, l, t, r, b);  out: [B, R, 3] = (t, r, b), zero-padded.

#define NMS_N      2048
#define NMS_R      100
#define NT         256
#define SEL_CAP    256
#define MAT_N      160
#define MAT_COLS   5
#define MAT_STRIDE 7
#define T_SEL      0.90f
#define U_TSEL     0x3F666666u   // bits of 0.90f

typedef unsigned long long ull;

__device__ __forceinline__ unsigned int float_to_ordered(float f) {
    unsigned int u = __float_as_uint(f);
    return (u & 0x80000000u) ? ~u : (u | 0x80000000u);
}
__device__ __forceinline__ unsigned umin32(unsigned a, unsigned b) { return a < b ? a : b; }
__device__ __forceinline__ unsigned umax32(unsigned a, unsigned b) { return a > b ? a : b; }

// suppress cb if inter(kb, cb) >= hh (= 0.5 * area(cb)); sentinel kb -> false
__device__ __forceinline__ bool iou_sup(const float4 kb, const float4 cb, float hh) {
    float il = fmaxf(kb.x, cb.x);
    float it = fmaxf(kb.y, cb.y);
    float ir = fminf(kb.z, cb.z);
    float ib = fminf(kb.w, cb.w);
    return fmaxf(0.0f, ir - il) * fmaxf(0.0f, ib - it) >= hh;
}
__device__ __forceinline__ void selset(float4& d, const float4 s, bool p) {
    d.x = p ? s.x : d.x; d.y = p ? s.y : d.y;
    d.z = p ? s.z : d.z; d.w = p ? s.w : d.w;
}

__global__ __launch_bounds__(NT, 1)
void nms_kernel(const float* __restrict__ pred, float* __restrict__ out) {
    // 16KB pool, aliased:
    //   fast path: selKeys32[256] (1KB @0) | supMat[160*7] (4.4KB @4KB)
    //   fallback : fullKeys[2048] (16KB)
    __shared__ __align__(16) ull pool[2048];
    unsigned*     selKeys32 = (unsigned*)pool;              // [256]
    unsigned int* supMat    = (unsigned int*)(pool + 512);  // [160*7], byte off 4KB
    ull*          fullKeys  = pool;

    __shared__ __align__(16) float4 sortedBoxes[SEL_CAP];
    __shared__ float sortedHalf[SEL_CAP];
    __shared__ __align__(16) float4 keptBoxes[136];
    __shared__ float keptVals[NMS_R * 3];
    __shared__ int   selCount, sh_nkept;

    const int b    = blockIdx.x;
    const int tid  = threadIdx.x;
    const int lane = tid & 31;
    const int w    = tid >> 5;
    const unsigned FULL = 0xFFFFFFFFu;
    const float* batch = pred + (size_t)b * NMS_N * 5;

    if (tid == 0) selCount = 0;
    selKeys32[tid] = 0xFFFFFFFFu;   // pre-pad: max key (e-field 2047, benign)

    // ---- Phase 1: wide vectorized load; extract 8 scores/thread ----
    float s[8];
    {
        const float4* src = (const float4*)(batch + (size_t)40 * tid);
        float4 v0 = __ldg(src + 0), v1 = __ldg(src + 1), v2 = __ldg(src + 2);
        float4 v3 = __ldg(src + 3), v5 = __ldg(src + 5), v6 = __ldg(src + 6);
        float4 v7 = __ldg(src + 7), v8 = __ldg(src + 8);
        s[0] = v0.x; s[1] = v1.y; s[2] = v2.z; s[3] = v3.w;
        s[4] = v5.x; s[5] = v6.y; s[6] = v7.z; s[7] = v8.w;
    }
    __syncthreads();   // selCount init + key pre-pad visible

    // ---- Phase 2: fixed-threshold warp-aggregated compaction (keys only) ----
    #pragma unroll
    for (int j = 0; j < 8; j++) {
        bool sel = s[j] >= T_SEL;
        unsigned m = __ballot_sync(FULL, sel);
        int cnt = __popc(m);
        int basep = 0;
        int leader = __ffs(m) - 1;
        if (cnt > 0 && lane == leader) basep = atomicAdd(&selCount, cnt);
        basep = __shfl_sync(FULL, basep, leader < 0 ? 0 : leader);
        if (sel) {
            int pos = basep + __popc(m & ((1u << lane) - 1u));
            if (pos < SEL_CAP) {
                unsigned e = 8 * tid + j;
                unsigned delta = __float_as_uint(s[j]) - U_TSEL;   // < 2^21
                selKeys32[pos] = ((0x1FFFFFu - delta) << 11) | e;  // asc = score desc, idx asc
            }
        }
    }
    __syncthreads();
    const int nsel = selCount;
    const bool fb1 = (nsel > SEL_CAP);   // uniform across block

    #define REG_PASS32(k, j) do {                                               \
        if ((j) == 32) {                                                        \
            bool dir = ((xa & (k)) == 0);                                       \
            if ((a > c) == dir) { unsigned t_ = a; a = c; c = t_; }             \
        } else {                                                                \
            unsigned pa = __shfl_xor_sync(FULL, a, (j));                        \
            unsigned pc = __shfl_xor_sync(FULL, c, (j));                        \
            bool low = ((lane & (j)) == 0);                                     \
            bool da  = ((xa & (k)) == 0);                                       \
            bool dc  = ((xb & (k)) == 0);                                       \
            a = (low == da) ? umin32(a, pa) : umax32(a, pa);                    \
            c = (low == dc) ? umin32(c, pc) : umax32(c, pc);                    \
        }                                                                       \
    } while (0)

    if (!fb1) {
        // ---- Phase 3: hybrid bitonic sort of 256 u32 keys (warps 0-3) ----
        const int xa = (w << 6) | lane;
        const int xb = xa + 32;
        unsigned a = 0, c = 0;
        if (w < 4) {
            a = selKeys32[xa]; c = selKeys32[xb];
            #pragma unroll
            for (int k = 2; k <= 64; k <<= 1) {
                #pragma unroll
                for (int j = (k > 32 ? 32 : (k >> 1)); j >= 1; j >>= 1) REG_PASS32(k, j);
            }
        }
        #pragma unroll
        for (int k = 128; k <= SEL_CAP; k <<= 1) {
            if (w < 4) { selKeys32[xa] = a; selKeys32[xb] = c; }
            __syncthreads();
            for (int j = (k >> 1); j >= 64; j >>= 1) {
                if (tid < SEL_CAP / 2) {
                    unsigned int i  = tid;
                    unsigned int lo = ((i & ~(j - 1)) << 1) | (i & (j - 1));
                    unsigned int hi = lo | j;
                    unsigned u = selKeys32[lo], v = selKeys32[hi];
                    bool dir = ((lo & k) == 0);
                    if ((u > v) == dir) { selKeys32[lo] = v; selKeys32[hi] = u; }
                }
                __syncthreads();
            }
            if (w < 4) {
                a = selKeys32[xa]; c = selKeys32[xb];
                #pragma unroll
                for (int j = 32; j >= 1; j >>= 1) REG_PASS32(k, j);
            }
        }
        // Fused permute: gather boxes from global (L2-hit) in sorted order
        if (w < 4) {
            #pragma unroll
            for (int q = 0; q < 2; q++) {
                int dst = q == 0 ? xa : xb;
                unsigned key = q == 0 ? a : c;
                int e = (int)(key & 0x7FFu);
                const float* pp = batch + (size_t)e * 5;
                float l  = __ldg(pp + 1), t  = __ldg(pp + 2);
                float r  = __ldg(pp + 3), bo = __ldg(pp + 4);
                sortedBoxes[dst] = make_float4(l, t, r, bo);
                sortedHalf[dst]  = 0.5f * (r - l) * (bo - t);
            }
        }
        __syncthreads();

        // ---- Phase 4: balanced triangular suppression matrix (all 8 warps) ----
        for (int slot = tid; slot < MAT_N * MAT_COLS; slot += NT) {
            int wb = slot / MAT_N;
            int i  = slot - wb * MAT_N;
            int jbase = wb << 5;
            int jend = i - jbase; jend = jend > 32 ? 32 : jend;
            unsigned mm = 0;
            if (jend > 0) {
                float4 cb = sortedBoxes[i];
                float  hh = sortedHalf[i];
                for (int jo = 0; jo < jend; jo++) {
                    if (iou_sup(sortedBoxes[jbase + jo], cb, hh)) mm |= 1u << jo;
                }
            }
            supMat[i * MAT_STRIDE + wb] = mm;
        }
        __syncthreads();

        // ---- Phase 5: bitwise greedy resolution (warp 0) ----
        if (w == 0) {
            unsigned KM0 = 0, KM1 = 0, KM2 = 0, KM3 = 0, KM4 = 0;
            int nkept = 0;
            const unsigned below = (1u << lane) - 1u;
            int matLim = nsel < MAT_N ? nsel : MAT_N;
            int nblk = (matLim + 31) >> 5;

            for (int blk = 0; blk < nblk && nkept < NMS_R; blk++) {
                int i = (blk << 5) + lane;
                bool valid = i < matLim;
                const unsigned* row = supMat + i * MAT_STRIDE;
                unsigned m0 = row[0], m1 = row[1], m2 = row[2];
                unsigned m3 = row[3], m4 = row[4];
                unsigned sk = (m0 & KM0) | (m1 & KM1) | (m2 & KM2)
                            | (m3 & KM3) | (m4 & KM4);
                unsigned inb = blk == 0 ? m0 : blk == 1 ? m1 : blk == 2 ? m2
                             : blk == 3 ? m3 : m4;
                unsigned base = __ballot_sync(FULL, valid && sk == 0u);
                unsigned K = base;
                #pragma unroll 1
                for (int it = 0; it < 32; it++) {
                    bool alive = ((base >> lane) & 1u) && ((inb & K) == 0u);
                    unsigned Kn = __ballot_sync(FULL, alive);
                    if (Kn == K) break;
                    K = Kn;
                }
                bool kept = (K >> lane) & 1u;
                int  pos  = nkept + __popc(K & below);
                float4 cb = sortedBoxes[i];
                if (kept) keptBoxes[pos] = cb;
                if (kept && pos < NMS_R) {
                    keptVals[pos * 3 + 0] = cb.y;
                    keptVals[pos * 3 + 1] = cb.z;
                    keptVals[pos * 3 + 2] = cb.w;
                }
                KM0 |= (blk == 0) ? K : 0u; KM1 |= (blk == 1) ? K : 0u;
                KM2 |= (blk == 2) ? K : 0u; KM3 |= (blk == 3) ? K : 0u;
                KM4 |= (blk == 4) ? K : 0u;
                nkept += __popc(K);
            }

            // Continuation beyond MAT_N (rare): warp-parallel blocks
            int cd = MAT_N;
            while (cd < nsel && nkept < NMS_R) {
                int ci = cd + lane;
                bool valid = ci < nsel;
                int cidx = ci & (SEL_CAP - 1);
                float4 cb = sortedBoxes[cidx];
                float  hh = sortedHalf[cidx];
                bool supk = false;
                for (int kj = 0; kj < nkept; kj++)
                    supk |= iou_sup(keptBoxes[kj], cb, hh);
                unsigned supBy = 0;
                #pragma unroll 8
                for (int j = 0; j < 32; j++) {
                    int jj = (cd + j) & (SEL_CAP - 1);
                    float4 ob = sortedBoxes[jj];
                    if (iou_sup(ob, cb, hh)) supBy |= (1u << j);
                }
                supBy &= ~(1u << lane);
                unsigned base = __ballot_sync(FULL, valid && !supk);
                unsigned K = base;
                #pragma unroll 1
                for (int it = 0; it < 32; it++) {
                    bool alive = ((base >> lane) & 1u) && ((supBy & K & below) == 0u);
                    unsigned Kn = __ballot_sync(FULL, alive);
                    if (Kn == K) break;
                    K = Kn;
                }
                bool kept = (K >> lane) & 1u;
                int  pos  = nkept + __popc(K & below);
                if (kept && pos < 136) keptBoxes[pos] = cb;
                if (kept && pos < NMS_R) {
                    keptVals[pos * 3 + 0] = cb.y;
                    keptVals[pos * 3 + 1] = cb.z;
                    keptVals[pos * 3 + 2] = cb.w;
                }
                __syncwarp();
                nkept += __popc(K);
                cd += 32;
            }
            if (lane == 0) sh_nkept = (nkept < NMS_R) ? nkept : NMS_R;
        }
        __syncthreads();
    }

    // fallback condition: overflow OR too few kept (uniform decision)
    const bool fb = fb1 || (sh_nkept < NMS_R);

    // ---- Fallback: full 2048 sort + greedy (exact, rarely taken) ----
    if (fb) {
        const float4 sent = make_float4(1e30f, 1e30f, -1e30f, -1e30f);
        #pragma unroll
        for (int j = 0; j < 8; j++) {
            int e = 8 * tid + j;
            fullKeys[e] = ((ull)(~float_to_ordered(s[j])) << 32) | (unsigned)e;
        }
        __syncthreads();
        for (unsigned int k = 2; k <= NMS_N; k <<= 1) {
            for (unsigned int j = k >> 1; j > 0; j >>= 1) {
                #pragma unroll
                for (int p = 0; p < 4; p++) {
                    unsigned int i  = tid + p * NT;
                    unsigned int lo = ((i & ~(j - 1)) << 1) | (i & (j - 1));
                    unsigned int hi = lo | j;
                    ull u = fullKeys[lo], v = fullKeys[hi];
                    bool dir = ((lo & k) == 0);
                    if ((u > v) == dir) { fullKeys[lo] = v; fullKeys[hi] = u; }
                }
                __syncthreads();
            }
        }
        if (w == 0) {
            float4 k0s = sent, k1s = sent, k2s = sent, k3s = sent;
            int nkept = 0;
            int idx_n = (int)(fullKeys[0] & 0x7FF);
            const float* pn = batch + (size_t)idx_n * 5;
            float l_n = __ldg(pn + 1), t_n = __ldg(pn + 2), r_n = __ldg(pn + 3), b_n = __ldg(pn + 4);
            for (int cd = 0; cd < NMS_N && nkept < NMS_R; ++cd) {
                float4 cb = make_float4(l_n, t_n, r_n, b_n);
                if (cd + 1 < NMS_N) {
                    idx_n = (int)(fullKeys[cd + 1] & 0x7FF);
                    const float* p2 = batch + (size_t)idx_n * 5;
                    l_n = __ldg(p2 + 1); t_n = __ldg(p2 + 2); r_n = __ldg(p2 + 3); b_n = __ldg(p2 + 4);
                }
                float hh = 0.5f * (cb.z - cb.x) * (cb.w - cb.y);
                bool sup = iou_sup(k0s, cb, hh) | iou_sup(k1s, cb, hh)
                         | iou_sup(k2s, cb, hh) | iou_sup(k3s, cb, hh);
                unsigned bal = __ballot_sync(FULL, sup);
                bool keep = (bal == 0u);
                bool m = keep && ((nkept & 31) == lane);
                int  sl = nkept >> 5;
                selset(k0s, cb, m && sl == 0);
                selset(k1s, cb, m && sl == 1);
                selset(k2s, cb, m && sl == 2);
                selset(k3s, cb, m && sl == 3);
                if (keep && lane == 0) {
                    keptVals[nkept * 3 + 0] = cb.y;
                    keptVals[nkept * 3 + 1] = cb.z;
                    keptVals[nkept * 3 + 2] = cb.w;
                }
                nkept += keep ? 1 : 0;
            }
            if (lane == 0) sh_nkept = nkept;
        }
        __syncthreads();
    }

    // ---- Output: [R,3], zero-padded ----
    int nk = sh_nkept;
    for (int o = tid; o < NMS_R * 3; o += NT) {
        int slot = o / 3;
        out[(size_t)b * NMS_R * 3 + o] = (slot < nk) ? keptVals[o] : 0.0f;
    }
}

extern "C" void kernel_launch(void* const* d_in, const int* in_sizes, int n_in,
                              void* d_out, int out_size) {
    const float* pred = (const float*)d_in[0];
    float* out = (float*)d_out;
    nms_kernel<<<32, NT>>>(pred, out);
}

// round 12
// speedup vs baseline: 1.0514x; 1.0514x over previous
#include <cuda_runtime.h>
#include <cuda_bf16.h>

// NMS: B=32, N=2048, keep first R=100 surviving boxes (greedy, score-desc).
// pred: [B, N, 5] = (score, l, t, r, b);  out: [B, R, 3] = (t, r, b), zero-padded.

#define NMS_N      2048
#define NMS_R      100
#define NT         256
#define SEL_CAP    256
#define MAT_N      160
#define MAT_COLS   5
#define MAT_STRIDE 7
#define T_SEL      0.90f
#define U_TSEL     0x3F666666u   // bits of 0.90f

typedef unsigned long long ull;

__device__ __forceinline__ unsigned int float_to_ordered(float f) {
    unsigned int u = __float_as_uint(f);
    return (u & 0x80000000u) ? ~u : (u | 0x80000000u);
}

// suppress cb if inter(kb, cb) >= hh (= 0.5 * area(cb)); sentinel kb -> false
__device__ __forceinline__ bool iou_sup(const float4 kb, const float4 cb, float hh) {
    float il = fmaxf(kb.x, cb.x);
    float it = fmaxf(kb.y, cb.y);
    float ir = fminf(kb.z, cb.z);
    float ib = fminf(kb.w, cb.w);
    return fmaxf(0.0f, ir - il) * fmaxf(0.0f, ib - it) >= hh;
}
__device__ __forceinline__ void selset(float4& d, const float4 s, bool p) {
    d.x = p ? s.x : d.x; d.y = p ? s.y : d.y;
    d.z = p ? s.z : d.z; d.w = p ? s.w : d.w;
}

__global__ __launch_bounds__(NT, 1)
void nms_kernel(const float* __restrict__ pred, float* __restrict__ out) {
    // 16KB pool, aliased:
    //   fast path: selKeys32[256] (1KB @0) | supMat[160*7] (4.4KB @4KB)
    //   fallback : fullKeys[2048] (16KB)
    __shared__ __align__(16) ull pool[2048];
    unsigned*     selKeys32 = (unsigned*)pool;              // [256]
    unsigned int* supMat    = (unsigned int*)(pool + 512);  // [160*7], byte off 4KB
    ull*          fullKeys  = pool;

    __shared__ __align__(16) float4 sortedBoxes[SEL_CAP];
    __shared__ float sortedHalf[SEL_CAP];
    __shared__ __align__(16) float4 keptBoxes[136];
    __shared__ float keptVals[NMS_R * 3];
    __shared__ int   selCount, sh_nkept;

    const int b    = blockIdx.x;
    const int tid  = threadIdx.x;
    const int lane = tid & 31;
    const int w    = tid >> 5;
    const unsigned FULL = 0xFFFFFFFFu;
    const float* batch = pred + (size_t)b * NMS_N * 5;

    if (tid == 0) selCount = 0;
    selKeys32[tid] = 0xFFFFFFFFu;   // pre-pad: max key (e-field 2047, benign)

    // ---- Phase 1: wide vectorized load; extract 8 scores/thread ----
    float s[8];
    {
        const float4* src = (const float4*)(batch + (size_t)40 * tid);
        float4 v0 = __ldg(src + 0), v1 = __ldg(src + 1), v2 = __ldg(src + 2);
        float4 v3 = __ldg(src + 3), v5 = __ldg(src + 5), v6 = __ldg(src + 6);
        float4 v7 = __ldg(src + 7), v8 = __ldg(src + 8);
        s[0] = v0.x; s[1] = v1.y; s[2] = v2.z; s[3] = v3.w;
        s[4] = v5.x; s[5] = v6.y; s[6] = v7.z; s[7] = v8.w;
    }
    __syncthreads();   // selCount init + key pre-pad visible

    // ---- Phase 2: fixed-threshold warp-aggregated compaction (keys only) ----
    #pragma unroll
    for (int j = 0; j < 8; j++) {
        bool sel = s[j] >= T_SEL;
        unsigned m = __ballot_sync(FULL, sel);
        int cnt = __popc(m);
        int basep = 0;
        int leader = __ffs(m) - 1;
        if (cnt > 0 && lane == leader) basep = atomicAdd(&selCount, cnt);
        basep = __shfl_sync(FULL, basep, leader < 0 ? 0 : leader);
        if (sel) {
            int pos = basep + __popc(m & ((1u << lane) - 1u));
            if (pos < SEL_CAP) {
                unsigned e = 8 * tid + j;
                unsigned delta = __float_as_uint(s[j]) - U_TSEL;   // < 2^21
                selKeys32[pos] = ((0x1FFFFFu - delta) << 11) | e;  // asc = score desc, idx asc
            }
        }
    }
    __syncthreads();
    const int nsel = selCount;
    const bool fb1 = (nsel > SEL_CAP);   // uniform across block

    if (!fb1) {
        // ---- Phase 3: counting-rank sort + fused gather/scatter (all 8 warps) ----
        // rank = #{keys < myKey}; keys unique except pads (identical -> same rank,
        // same box -> benign same-value race). Box gather issues first (L1 hit)
        // so LDG latency hides under the 64x LDS.128 compare loop.
        {
            unsigned myKey = selKeys32[tid];
            int e = (int)(myKey & 0x7FFu);
            const float* pp = batch + (size_t)e * 5;
            float l  = __ldg(pp + 1), t  = __ldg(pp + 2);
            float r  = __ldg(pp + 3), bo = __ldg(pp + 4);
            int rank = 0;
            const uint4* keys4 = (const uint4*)selKeys32;
            #pragma unroll 16
            for (int j = 0; j < SEL_CAP / 4; j++) {
                uint4 kk = keys4[j];
                rank += (kk.x < myKey) + (kk.y < myKey)
                      + (kk.z < myKey) + (kk.w < myKey);
            }
            sortedBoxes[rank] = make_float4(l, t, r, bo);
            sortedHalf[rank]  = 0.5f * (r - l) * (bo - t);
        }
        __syncthreads();

        // ---- Phase 4: balanced triangular suppression matrix (all 8 warps) ----
        for (int slot = tid; slot < MAT_N * MAT_COLS; slot += NT) {
            int wb = slot / MAT_N;
            int i  = slot - wb * MAT_N;
            int jbase = wb << 5;
            int jend = i - jbase; jend = jend > 32 ? 32 : jend;
            unsigned mm = 0;
            if (jend > 0) {
                float4 cb = sortedBoxes[i];
                float  hh = sortedHalf[i];
                for (int jo = 0; jo < jend; jo++) {
                    if (iou_sup(sortedBoxes[jbase + jo], cb, hh)) mm |= 1u << jo;
                }
            }
            supMat[i * MAT_STRIDE + wb] = mm;
        }
        __syncthreads();

        // ---- Phase 5: bitwise greedy resolution (warp 0) ----
        if (w == 0) {
            unsigned KM0 = 0, KM1 = 0, KM2 = 0, KM3 = 0, KM4 = 0;
            int nkept = 0;
            const unsigned below = (1u << lane) - 1u;
            int matLim = nsel < MAT_N ? nsel : MAT_N;
            int nblk = (matLim + 31) >> 5;

            for (int blk = 0; blk < nblk && nkept < NMS_R; blk++) {
                int i = (blk << 5) + lane;
                bool valid = i < matLim;
                const unsigned* row = supMat + i * MAT_STRIDE;
                unsigned m0 = row[0], m1 = row[1], m2 = row[2];
                unsigned m3 = row[3], m4 = row[4];
                unsigned sk = (m0 & KM0) | (m1 & KM1) | (m2 & KM2)
                            | (m3 & KM3) | (m4 & KM4);
                unsigned inb = blk == 0 ? m0 : blk == 1 ? m1 : blk == 2 ? m2
                             : blk == 3 ? m3 : m4;
                unsigned base = __ballot_sync(FULL, valid && sk == 0u);
                unsigned K = base;
                #pragma unroll 1
                for (int it = 0; it < 32; it++) {
                    bool alive = ((base >> lane) & 1u) && ((inb & K) == 0u);
                    unsigned Kn = __ballot_sync(FULL, alive);
                    if (Kn == K) break;
                    K = Kn;
                }
                bool kept = (K >> lane) & 1u;
                int  pos  = nkept + __popc(K & below);
                float4 cb = sortedBoxes[i];
                if (kept) keptBoxes[pos] = cb;
                if (kept && pos < NMS_R) {
                    keptVals[pos * 3 + 0] = cb.y;
                    keptVals[pos * 3 + 1] = cb.z;
                    keptVals[pos * 3 + 2] = cb.w;
                }
                KM0 |= (blk == 0) ? K : 0u; KM1 |= (blk == 1) ? K : 0u;
                KM2 |= (blk == 2) ? K : 0u; KM3 |= (blk == 3) ? K : 0u;
                KM4 |= (blk == 4) ? K : 0u;
                nkept += __popc(K);
            }

            // Continuation beyond MAT_N (rare): warp-parallel blocks.
            // supBy masked to valid in-block lanes (slots >= nsel are stale).
            int cd = MAT_N;
            while (cd < nsel && nkept < NMS_R) {
                int rem = nsel - cd;
                unsigned validMask = rem >= 32 ? FULL : ((1u << rem) - 1u);
                int ci = cd + lane;
                bool valid = ci < nsel;
                int cidx = ci & (SEL_CAP - 1);
                float4 cb = sortedBoxes[cidx];
                float  hh = sortedHalf[cidx];
                bool supk = false;
                for (int kj = 0; kj < nkept; kj++)
                    supk |= iou_sup(keptBoxes[kj], cb, hh);
                unsigned supBy = 0;
                #pragma unroll 8
                for (int j = 0; j < 32; j++) {
                    int jj = (cd + j) & (SEL_CAP - 1);
                    float4 ob = sortedBoxes[jj];
                    if (iou_sup(ob, cb, hh)) supBy |= (1u << j);
                }
                supBy &= validMask & ~(1u << lane);
                unsigned base = __ballot_sync(FULL, valid && !supk);
                unsigned K = base;
                #pragma unroll 1
                for (int it = 0; it < 32; it++) {
                    bool alive = ((base >> lane) & 1u) && ((supBy & K & below) == 0u);
                    unsigned Kn = __ballot_sync(FULL, alive);
                    if (Kn == K) break;
                    K = Kn;
                }
                bool kept = (K >> lane) & 1u;
                int  pos  = nkept + __popc(K & below);
                if (kept && pos < 136) keptBoxes[pos] = cb;
                if (kept && pos < NMS_R) {
                    keptVals[pos * 3 + 0] = cb.y;
                    keptVals[pos * 3 + 1] = cb.z;
                    keptVals[pos * 3 + 2] = cb.w;
                }
                __syncwarp();
                nkept += __popc(K);
                cd += 32;
            }
            if (lane == 0) sh_nkept = (nkept < NMS_R) ? nkept : NMS_R;
        }
        __syncthreads();
    }

    // fallback condition: overflow OR too few kept (uniform decision)
    const bool fb = fb1 || (sh_nkept < NMS_R);

    // ---- Fallback: full 2048 sort + greedy (exact, rarely taken) ----
    if (fb) {
        const float4 sent = make_float4(1e30f, 1e30f, -1e30f, -1e30f);
        #pragma unroll
        for (int j = 0; j < 8; j++) {
            int e = 8 * tid + j;
            fullKeys[e] = ((ull)(~float_to_ordered(s[j])) << 32) | (unsigned)e;
        }
        __syncthreads();
        for (unsigned int k = 2; k <= NMS_N; k <<= 1) {
            for (unsigned int j = k >> 1; j > 0; j >>= 1) {
                #pragma unroll
                for (int p = 0; p < 4; p++) {
                    unsigned int i  = tid + p * NT;
                    unsigned int lo = ((i & ~(j - 1)) << 1) | (i & (j - 1));
                    unsigned int hi = lo | j;
                    ull u = fullKeys[lo], v = fullKeys[hi];
                    bool dir = ((lo & k) == 0);
                    if ((u > v) == dir) { fullKeys[lo] = v; fullKeys[hi] = u; }
                }
                __syncthreads();
            }
        }
        if (w == 0) {
            float4 k0s = sent, k1s = sent, k2s = sent, k3s = sent;
            int nkept = 0;
            int idx_n = (int)(fullKeys[0] & 0x7FF);
            const float* pn = batch + (size_t)idx_n * 5;
            float l_n = __ldg(pn + 1), t_n = __ldg(pn + 2), r_n = __ldg(pn + 3), b_n = __ldg(pn + 4);
            for (int cd = 0; cd < NMS_N && nkept < NMS_R; ++cd) {
                float4 cb = make_float4(l_n, t_n, r_n, b_n);
                if (cd + 1 < NMS_N) {
                    idx_n = (int)(fullKeys[cd + 1] & 0x7FF);
                    const float* p2 = batch + (size_t)idx_n * 5;
                    l_n = __ldg(p2 + 1); t_n = __ldg(p2 + 2); r_n = __ldg(p2 + 3); b_n = __ldg(p2 + 4);
                }
                float hh = 0.5f * (cb.z - cb.x) * (cb.w - cb.y);
                bool sup = iou_sup(k0s, cb, hh) | iou_sup(k1s, cb, hh)
                         | iou_sup(k2s, cb, hh) | iou_sup(k3s, cb, hh);
                unsigned bal = __ballot_sync(FULL, sup);
                bool keep = (bal == 0u);
                bool m = keep && ((nkept & 31) == lane);
                int  sl = nkept >> 5;
                selset(k0s, cb, m && sl == 0);
                selset(k1s, cb, m && sl == 1);
                selset(k2s, cb, m && sl == 2);
                selset(k3s, cb, m && sl == 3);
                if (keep && lane == 0) {
                    keptVals[nkept * 3 + 0] = cb.y;
                    keptVals[nkept * 3 + 1] = cb.z;
                    keptVals[nkept * 3 + 2] = cb.w;
                }
                nkept += keep ? 1 : 0;
            }
            if (lane == 0) sh_nkept = nkept;
        }
        __syncthreads();
    }

    // ---- Output: [R,3], zero-padded ----
    int nk = sh_nkept;
    for (int o = tid; o < NMS_R * 3; o += NT) {
        int slot = o / 3;
        out[(size_t)b * NMS_R * 3 + o] = (slot < nk) ? keptVals[o] : 0.0f;
    }
}

extern "C" void kernel_launch(void* const* d_in, const int* in_sizes, int n_in,
                              void* d_out, int out_size) {
    const float* pred = (const float*)d_in[0];
    float* out = (float*)d_out;
    nms_kernel<<<32, NT>>>(pred, out);
}